// round 3
// baseline (speedup 1.0000x reference)
#include <cuda_runtime.h>
#include <math.h>

// ---------------------------------------------------------------------------
// Problem constants
// ---------------------------------------------------------------------------
constexpr int H_    = 93;
constexpr int W_    = 44;
constexpr int HW_   = H_ * W_;      // 4092
constexpr int B_    = 8;
constexpr int HID_  = 128;
constexpr int LAT_  = 1024;
constexpr int MAXN_ = 24;
constexpr int OFF1  = B_ * HW_ * 2; // 65472  (start of mask_indices, as float)
constexpr int OFF2  = 2 * OFF1;     // 130944 (start of valid_mask, as float)

// ---------------------------------------------------------------------------
// Scratch (__device__ globals: no allocation allowed)
// ---------------------------------------------------------------------------
__device__ float g_lc  [B_ * HID_];           // gelu(latent @ Wl + bl)
__device__ float g_T   [B_ * 9 * HID_];       // per-tap latent*Wt
__device__ float g_G9  [B_ * 9 * HID_];       // 9-class post GN+gelu
__device__ float g_F25 [B_ * 25 * HID_];      // 25-class feats (post conv2+gelu)
__device__ float g_s25 [B_ * 25];             // class attention scores
__device__ float g_Y   [B_ * 25 * HID_];      // F25 @ W1[:128]
__device__ float g_base[B_ * HID_];           // latent_cond @ W1[128:] + b1
__device__ float g_Pint[B_ * 2];              // interior-position prediction
__device__ float g_preds[B_ * HW_ * 2];       // per-position predictions

__device__ __forceinline__ float gelu_(float x) {
    return 0.5f * x * (1.0f + erff(x * 0.70710678118654752440f));
}

// rowmap[out_row_class][tap] -> input row-class (0=top,1=mid,2=bot), -1 = tap OOB
__constant__ int c_map[5][3] = {
    {-1, 0, 1},  // r = 0
    { 0, 1, 1},  // r = 1
    { 1, 1, 1},  // interior
    { 1, 1, 2},  // r = H-2
    { 1, 2,-1},  // r = H-1
};

// ---------------------------------------------------------------------------
// K1: latent_cond = gelu(latent @ Wl + bl)          grid(B), block(HID)
// ---------------------------------------------------------------------------
__global__ void k_latent(const float* __restrict__ lat,
                         const float* __restrict__ Wl,
                         const float* __restrict__ bl) {
    int b = blockIdx.x, o = threadIdx.x;
    __shared__ float ls[LAT_];
    for (int i = o; i < LAT_; i += HID_) ls[i] = lat[b * LAT_ + i];
    __syncthreads();
    float acc = bl[o];
    for (int i = 0; i < LAT_; i++) acc = fmaf(ls[i], Wl[i * HID_ + o], acc);
    g_lc[b * HID_ + o] = gelu_(acc);
}

// ---------------------------------------------------------------------------
// K2: T[b,tap,o] = sum_i lc[b,i] * Wt[tap,i,o]      grid(B,9), block(HID)
// ---------------------------------------------------------------------------
__global__ void k_taps(const float* __restrict__ Wt) {
    int b = blockIdx.x, t = blockIdx.y, o = threadIdx.x;
    __shared__ float ls[HID_];
    ls[o] = g_lc[b * HID_ + o];
    __syncthreads();
    const float* w = Wt + (size_t)t * HID_ * HID_;
    float acc = 0.f;
    for (int i = 0; i < HID_; i++) acc = fmaf(ls[i], w[i * HID_ + o], acc);
    g_T[(b * 9 + t) * HID_ + o] = acc;
}

// ---------------------------------------------------------------------------
// K3: 9-class conv_transpose values + area-weighted GroupNorm(8) + gelu
//     grid(B), block(HID)  -- groups are 16 consecutive channels = 16 lanes
// ---------------------------------------------------------------------------
__global__ void k_gn(const float* __restrict__ bt,
                     const float* __restrict__ g1,
                     const float* __restrict__ b1g) {
    int b = blockIdx.x, o = threadIdx.x;
    float Tl[9];
    for (int t = 0; t < 9; t++) Tl[t] = g_T[(b * 9 + t) * HID_ + o];
    float btv = bt[o];

    float c9[9];
    for (int rc = 0; rc < 3; rc++) {
        for (int cc = 0; cc < 3; cc++) {
            float s = btv;
            for (int kh = 0; kh < 3; kh++) {
                if ((rc == 0 && kh == 0) || (rc == 2 && kh == 2)) continue;
                for (int kw = 0; kw < 3; kw++) {
                    if ((cc == 0 && kw == 0) || (cc == 2 && kw == 2)) continue;
                    s += Tl[kh * 3 + kw];
                }
            }
            c9[rc * 3 + cc] = s;
        }
    }

    // areas: rows {1, H-2, 1} x cols {1, W-2, 1}
    const float rowcnt[3] = {1.f, (float)(H_ - 2), 1.f};
    const float colcnt[3] = {1.f, (float)(W_ - 2), 1.f};
    float area[9];
    for (int rc = 0; rc < 3; rc++)
        for (int cc = 0; cc < 3; cc++)
            area[rc * 3 + cc] = rowcnt[rc] * colcnt[cc];

    const float inv = 1.0f / (16.0f * (float)HW_);
    float s = 0.f;
    for (int k = 0; k < 9; k++) s += area[k] * c9[k];
    for (int off = 8; off >= 1; off >>= 1) s += __shfl_xor_sync(0xffffffffu, s, off);
    float mean = s * inv;

    float d = 0.f;
    for (int k = 0; k < 9; k++) { float t = c9[k] - mean; d += area[k] * t * t; }
    for (int off = 8; off >= 1; off >>= 1) d += __shfl_xor_sync(0xffffffffu, d, off);
    float rstd = rsqrtf(d * inv + 1e-5f);

    float ga = g1[o], be = b1g[o];
    for (int k = 0; k < 9; k++)
        g_G9[(b * 9 + k) * HID_ + o] = gelu_((c9[k] - mean) * rstd * ga + be);
}

// ---------------------------------------------------------------------------
// K4: 25-class second conv + gelu                    grid(B,25), block(HID)
// ---------------------------------------------------------------------------
__global__ void k_conv2(const float* __restrict__ Wc,
                        const float* __restrict__ bc) {
    int b = blockIdx.x, cls = blockIdx.y, o = threadIdx.x;
    int orc = cls / 5, occ = cls % 5;
    __shared__ float gs[9 * HID_];
    for (int i = o; i < 9 * HID_; i += HID_) gs[i] = g_G9[b * 9 * HID_ + i];
    __syncthreads();

    float acc = bc[o];
    for (int kh = 0; kh < 3; kh++) {
        int ir = c_map[orc][kh];
        if (ir < 0) continue;
        for (int kw = 0; kw < 3; kw++) {
            int ic = c_map[occ][kw];
            if (ic < 0) continue;
            const float* gv = gs + (ir * 3 + ic) * HID_;
            const float* w  = Wc + (size_t)(kh * 3 + kw) * HID_ * HID_;
            for (int i = 0; i < HID_; i++) acc = fmaf(gv[i], w[i * HID_ + o], acc);
        }
    }
    g_F25[(b * 25 + cls) * HID_ + o] = gelu_(acc);
}

// ---------------------------------------------------------------------------
// K5a: Y[b,cls,:] = F25 @ W1[:128]  and  s25[b,cls] = F25 . Wa + ba
//      grid(B,25), block(HID)
// ---------------------------------------------------------------------------
__global__ void k_Ys(const float* __restrict__ Wa,
                     const float* __restrict__ ba,
                     const float* __restrict__ W1) {
    int b = blockIdx.x, cls = blockIdx.y, o = threadIdx.x;
    __shared__ float fs[HID_];
    __shared__ float red[4];
    fs[o] = g_F25[(b * 25 + cls) * HID_ + o];
    __syncthreads();

    float a = 0.f;
    for (int i = 0; i < HID_; i++) a = fmaf(fs[i], W1[i * HID_ + o], a);
    g_Y[(b * 25 + cls) * HID_ + o] = a;

    float sv = fs[o] * Wa[o];
    for (int off = 16; off >= 1; off >>= 1) sv += __shfl_xor_sync(0xffffffffu, sv, off);
    if ((o & 31) == 0) red[o >> 5] = sv;
    __syncthreads();
    if (o == 0) g_s25[b * 25 + cls] = red[0] + red[1] + red[2] + red[3] + ba[0];
}

// ---------------------------------------------------------------------------
// K5b: base[b,:] = lc @ W1[128:] + b1; Pint = MLP at interior class (12)
//      grid(B), block(HID)
// ---------------------------------------------------------------------------
__global__ void k_base(const float* __restrict__ W1,
                       const float* __restrict__ b1,
                       const float* __restrict__ W2,
                       const float* __restrict__ b2) {
    int b = blockIdx.x, o = threadIdx.x;
    float acc = b1[o];
    for (int i = 0; i < HID_; i++)
        acc = fmaf(g_lc[b * HID_ + i], W1[(HID_ + i) * HID_ + o], acc);
    g_base[b * HID_ + o] = acc;

    float h = gelu_(g_Y[(b * 25 + 12) * HID_ + o] + acc);
    __shared__ float r0[HID_], r1[HID_];
    r0[o] = h * W2[o * 2];
    r1[o] = h * W2[o * 2 + 1];
    __syncthreads();
    for (int st = 64; st >= 1; st >>= 1) {
        if (o < st) { r0[o] += r0[o + st]; r1[o] += r1[o + st]; }
        __syncthreads();
    }
    if (o == 0) {
        g_Pint[b * 2]     = r0[0] + b2[0];
        g_Pint[b * 2 + 1] = r1[0] + b2[1];
    }
}

// ---------------------------------------------------------------------------
// K6: per-position masked-neighbor attention + MLP -> g_preds
//     grid(HW), block(256) : warp w handles batch b = w
// ---------------------------------------------------------------------------
__global__ void k_attn(const int* __restrict__ mask,
                       const int* __restrict__ nidx,
                       const int* __restrict__ ncnt,
                       const float* __restrict__ W2,
                       const float* __restrict__ b2) {
    int p = blockIdx.x;
    int warp = threadIdx.x >> 5, lane = threadIdx.x & 31;
    int b = warp;
    int r = p / W_, c = p % W_;

    // interior: every neighbor is class 12; attention weights sum to 1 on it
    if (r >= 4 && r <= H_ - 5 && c >= 4 && c <= W_ - 5) {
        if (lane < 2) g_preds[(b * HW_ + p) * 2 + lane] = g_Pint[b * 2 + lane];
        return;
    }

    __shared__ float wc[8][25];
    if (lane < 25) wc[warp][lane] = 0.f;
    __syncwarp();

    bool has = lane < MAXN_;
    float logit = -3.0e38f;
    int cls = 0;
    if (has) {
        int idx = nidx[p * MAXN_ + lane];
        int rr = idx / W_, c2 = idx % W_;
        int rc = (rr == 0) ? 0 : (rr == 1) ? 1 : (rr == H_ - 2) ? 3 : (rr == H_ - 1) ? 4 : 2;
        int cc = (c2 == 0) ? 0 : (c2 == 1) ? 1 : (c2 == W_ - 2) ? 3 : (c2 == W_ - 1) ? 4 : 2;
        cls = rc * 5 + cc;
        bool valid = (lane < ncnt[p]) && (mask[b * HW_ + idx] == 0);
        logit = valid ? g_s25[b * 25 + cls] : -10000.0f;
    }
    float m = logit;
    for (int off = 16; off >= 1; off >>= 1) m = fmaxf(m, __shfl_xor_sync(0xffffffffu, m, off));
    float e = has ? expf(logit - m) : 0.f;   // underflows to exact 0 for invalid when any valid
    float se = e;
    for (int off = 16; off >= 1; off >>= 1) se += __shfl_xor_sync(0xffffffffu, se, off);
    float wgt = e / se;
    if (has && wgt != 0.f) atomicAdd(&wc[warp][cls], wgt);
    __syncwarp();

    float p0 = 0.f, p1 = 0.f;
    for (int k = 0; k < 4; k++) {
        int o = lane + 32 * k;
        float acc = g_base[b * HID_ + o];
        for (int cl = 0; cl < 25; cl++) {
            float wv = wc[warp][cl];
            if (wv != 0.f) acc = fmaf(wv, g_Y[(b * 25 + cl) * HID_ + o], acc);
        }
        float h = gelu_(acc);
        p0 = fmaf(h, W2[o * 2], p0);
        p1 = fmaf(h, W2[o * 2 + 1], p1);
    }
    for (int off = 16; off >= 1; off >>= 1) {
        p0 += __shfl_xor_sync(0xffffffffu, p0, off);
        p1 += __shfl_xor_sync(0xffffffffu, p1, off);
    }
    if (lane == 0) {
        g_preds[(b * HW_ + p) * 2]     = p0 + b2[0];
        g_preds[(b * HW_ + p) * 2 + 1] = p1 + b2[1];
    }
}

// ---------------------------------------------------------------------------
// K7: per-row prefix scan of mask, scatter packed outputs
//     grid(B), block(1024), 4 positions/thread
// ---------------------------------------------------------------------------
__global__ void k_pack(const int* __restrict__ mask, float* __restrict__ out) {
    int b = blockIdx.x, t = threadIdx.x;
    int lane = t & 31, warp = t >> 5;
    __shared__ int wsum[32];

    int base = t * 4;
    int m[4], loc[4];
    int s = 0;
    for (int j = 0; j < 4; j++) {
        int p = base + j;
        int mm = (p < HW_) ? (mask[b * HW_ + p] > 0) : 0;
        m[j] = mm; loc[j] = s; s += mm;
    }
    int v = s;  // warp inclusive scan of per-thread totals
    for (int off = 1; off < 32; off <<= 1) {
        int u = __shfl_up_sync(0xffffffffu, v, off);
        if (lane >= off) v += u;
    }
    if (lane == 31) wsum[warp] = v;
    __syncthreads();
    if (warp == 0) {
        int wv = wsum[lane];
        for (int off = 1; off < 32; off <<= 1) {
            int u = __shfl_up_sync(0xffffffffu, wv, off);
            if (lane >= off) wv += u;
        }
        wsum[lane] = wv;
    }
    __syncthreads();
    int excl = (v - s) + (warp > 0 ? wsum[warp - 1] : 0);

    for (int j = 0; j < 4; j++) {
        if (m[j]) {
            int p = base + j;
            int slot = excl + loc[j];
            out[(b * HW_ + slot) * 2]            = g_preds[(b * HW_ + p) * 2];
            out[(b * HW_ + slot) * 2 + 1]        = g_preds[(b * HW_ + p) * 2 + 1];
            out[OFF1 + (b * HW_ + slot) * 2]     = (float)(p / W_);
            out[OFF1 + (b * HW_ + slot) * 2 + 1] = (float)(p % W_);
            out[OFF2 + b * HW_ + slot]           = 1.0f;
        }
    }
}

// ---------------------------------------------------------------------------
// kernel_launch
// Inputs (metadata order): face_tensor, latent_token, mask_2d, nbr_indices,
// nbr_counts, Wl, bl, Wt, bt, g1, b1g, Wc, bc, Wa, ba, W1, b1, W2, b2
// ---------------------------------------------------------------------------
extern "C" void kernel_launch(void* const* d_in, const int* in_sizes, int n_in,
                              void* d_out, int out_size) {
    const float* latent = (const float*)d_in[1];
    const int*   mask   = (const int*)  d_in[2];
    const int*   nidx   = (const int*)  d_in[3];
    const int*   ncnt   = (const int*)  d_in[4];
    const float* Wl = (const float*)d_in[5];
    const float* bl = (const float*)d_in[6];
    const float* Wt = (const float*)d_in[7];
    const float* bt = (const float*)d_in[8];
    const float* g1 = (const float*)d_in[9];
    const float* b1g= (const float*)d_in[10];
    const float* Wc = (const float*)d_in[11];
    const float* bc = (const float*)d_in[12];
    const float* Wa = (const float*)d_in[13];
    const float* ba = (const float*)d_in[14];
    const float* W1 = (const float*)d_in[15];
    const float* b1 = (const float*)d_in[16];
    const float* W2 = (const float*)d_in[17];
    const float* b2 = (const float*)d_in[18];

    cudaMemsetAsync(d_out, 0, (size_t)out_size * sizeof(float));

    k_latent<<<B_, HID_>>>(latent, Wl, bl);
    { dim3 g(B_, 9);  k_taps <<<g, HID_>>>(Wt); }
    k_gn<<<B_, HID_>>>(bt, g1, b1g);
    { dim3 g(B_, 25); k_conv2<<<g, HID_>>>(Wc, bc); }
    { dim3 g(B_, 25); k_Ys   <<<g, HID_>>>(Wa, ba, W1); }
    k_base<<<B_, HID_>>>(W1, b1, W2, b2);
    k_attn<<<HW_, 256>>>(mask, nidx, ncnt, W2, b2);
    k_pack<<<B_, 1024>>>(mask, (float*)d_out);
}

// round 4
// speedup vs baseline: 1.4005x; 1.4005x over previous
#include <cuda_runtime.h>
#include <math.h>

// ---------------------------------------------------------------------------
// Problem constants
// ---------------------------------------------------------------------------
constexpr int H_    = 93;
constexpr int W_    = 44;
constexpr int HW_   = H_ * W_;      // 4092
constexpr int B_    = 8;
constexpr int HID_  = 128;
constexpr int LAT_  = 1024;
constexpr int MAXN_ = 24;
constexpr int OFF1  = B_ * HW_ * 2; // 65472  (start of mask_indices, as float)
constexpr int OFF2  = 2 * OFF1;     // 130944 (start of valid_mask, as float)
constexpr int NBORD = 1032;         // border positions (4-wide frame)

// ---------------------------------------------------------------------------
// Scratch (__device__ globals: no allocation allowed)
// ---------------------------------------------------------------------------
__device__ float g_lc  [B_ * HID_];           // gelu(latent @ Wl + bl)
__device__ float g_G9  [B_ * 9 * HID_];       // 9-class post GN+gelu
__device__ float g_F25 [B_ * 25 * HID_];      // 25-class feats (post conv2+gelu)
__device__ float g_s25 [B_ * 25];             // class attention scores
__device__ float g_Y   [B_ * 25 * HID_];      // F25 @ W1[:128]
__device__ float g_base[B_ * HID_];           // latent_cond @ W1[128:] + b1
__device__ float g_preds[B_ * HW_ * 2];       // border-position predictions

__device__ __forceinline__ float gelu_(float x) {
    return 0.5f * x * (1.0f + erff(x * 0.70710678118654752440f));
}

// rowmap[out_row_class][tap] -> input row-class (0=top,1=mid,2=bot), -1 = OOB
__constant__ int c_map[5][3] = {
    {-1, 0, 1},  // r = 0
    { 0, 1, 1},  // r = 1
    { 1, 1, 1},  // interior
    { 1, 1, 2},  // r = H-2
    { 1, 2,-1},  // r = H-1
};

// ---------------------------------------------------------------------------
// KA: per-batch fused chain:  lc = gelu(latent@Wl+bl)
//                             T[t] = lc @ Wt[t]
//                             G9  = gelu(GN(conv_transpose classes))
//     grid(B), block(1024)
// ---------------------------------------------------------------------------
__global__ __launch_bounds__(1024) void kA(const float* __restrict__ lat,
                                           const float* __restrict__ Wl,
                                           const float* __restrict__ bl,
                                           const float* __restrict__ Wt,
                                           const float* __restrict__ bt,
                                           const float* __restrict__ g1,
                                           const float* __restrict__ b1g) {
    int b = blockIdx.x, tid = threadIdx.x;
    __shared__ float ls[LAT_];
    __shared__ float red[1024];
    __shared__ float s_lc[HID_];
    __shared__ float s_T[9 * HID_];

    // --- latent GEMV, 8-way i-split ---
    ls[tid] = lat[b * LAT_ + tid];
    __syncthreads();
    int o = tid & 127, s = tid >> 7;
    {
        const float* w = Wl + (size_t)(s * 128) * HID_ + o;
        float acc = 0.f;
        #pragma unroll 8
        for (int i = 0; i < 128; i++) acc = fmaf(ls[s * 128 + i], w[i * HID_], acc);
        red[tid] = acc;
    }
    __syncthreads();
    for (int st = 4; st >= 1; st >>= 1) {
        if (s < st) red[tid] += red[tid + st * 128];
        __syncthreads();
    }
    if (tid < HID_) {
        float v = gelu_(red[tid] + bl[tid]);
        s_lc[tid] = v;
        g_lc[b * HID_ + tid] = v;
    }
    __syncthreads();

    // --- 9 taps: T[t,o] = lc . Wt[t,:,o]  (1152 outputs over 1024 threads) ---
    for (int idx = tid; idx < 9 * HID_; idx += 1024) {
        int t = idx >> 7, oo = idx & 127;
        const float* w = Wt + (size_t)t * HID_ * HID_ + oo;
        float acc = 0.f;
        #pragma unroll 8
        for (int i = 0; i < HID_; i++) acc = fmaf(s_lc[i], w[i * HID_], acc);
        s_T[idx] = acc;
    }
    __syncthreads();

    // --- 9-class values + area-weighted GroupNorm(8 groups of 16ch) + gelu ---
    if (tid < HID_) {
        float Tl[9];
        for (int t = 0; t < 9; t++) Tl[t] = s_T[t * HID_ + tid];
        float btv = bt[tid];

        float c9[9];
        for (int rc = 0; rc < 3; rc++)
            for (int cc = 0; cc < 3; cc++) {
                float sum = btv;
                for (int kh = 0; kh < 3; kh++) {
                    if ((rc == 0 && kh == 0) || (rc == 2 && kh == 2)) continue;
                    for (int kw = 0; kw < 3; kw++) {
                        if ((cc == 0 && kw == 0) || (cc == 2 && kw == 2)) continue;
                        sum += Tl[kh * 3 + kw];
                    }
                }
                c9[rc * 3 + cc] = sum;
            }

        const float rowcnt[3] = {1.f, (float)(H_ - 2), 1.f};
        const float colcnt[3] = {1.f, (float)(W_ - 2), 1.f};
        float area[9];
        for (int rc = 0; rc < 3; rc++)
            for (int cc = 0; cc < 3; cc++)
                area[rc * 3 + cc] = rowcnt[rc] * colcnt[cc];

        const float inv = 1.0f / (16.0f * (float)HW_);
        float sm = 0.f;
        for (int k = 0; k < 9; k++) sm += area[k] * c9[k];
        for (int off = 8; off >= 1; off >>= 1) sm += __shfl_xor_sync(0xffffffffu, sm, off);
        float mean = sm * inv;

        float d = 0.f;
        for (int k = 0; k < 9; k++) { float t = c9[k] - mean; d += area[k] * t * t; }
        for (int off = 8; off >= 1; off >>= 1) d += __shfl_xor_sync(0xffffffffu, d, off);
        float rstd = rsqrtf(d * inv + 1e-5f);

        float ga = g1[tid], be = b1g[tid];
        for (int k = 0; k < 9; k++)
            g_G9[(b * 9 + k) * HID_ + tid] = gelu_((c9[k] - mean) * rstd * ga + be);
    }
}

// ---------------------------------------------------------------------------
// KB: 25-class second conv + gelu; all 8 batches share one block's Wc reads
//     grid(25, 8) ; block 512 = 16 o x 8 b x 4 s(i-split)
// ---------------------------------------------------------------------------
__global__ __launch_bounds__(512) void kB(const float* __restrict__ Wc,
                                          const float* __restrict__ bc) {
    int cls = blockIdx.x;
    int orc = cls / 5, occ = cls % 5;
    int tid = threadIdx.x;
    int oo = tid & 15, b = (tid >> 4) & 7, s = tid >> 7;
    int o  = blockIdx.y * 16 + oo;

    __shared__ float gs[B_ * 9 * HID_];   // 36 KB: all batches' 9-class feats
    __shared__ float sp[512];
    for (int i = tid; i < B_ * 9 * HID_; i += 512) gs[i] = g_G9[i];
    __syncthreads();

    float acc = 0.f;
    for (int kh = 0; kh < 3; kh++) {
        int ir = c_map[orc][kh];
        if (ir < 0) continue;
        for (int kw = 0; kw < 3; kw++) {
            int ic = c_map[occ][kw];
            if (ic < 0) continue;
            const float* gv = gs + (b * 9 + ir * 3 + ic) * HID_ + s * 32;
            const float* w  = Wc + (size_t)(kh * 3 + kw) * HID_ * HID_ + (size_t)(s * 32) * HID_ + o;
            #pragma unroll
            for (int i = 0; i < 32; i++) acc = fmaf(gv[i], w[i * HID_], acc);
        }
    }
    sp[tid] = acc;
    __syncthreads();
    if (s < 2) sp[tid] += sp[tid + 256];
    __syncthreads();
    if (s == 0) {
        float v = sp[tid] + sp[tid + 128] + bc[o];
        g_F25[(b * 25 + cls) * HID_ + o] = gelu_(v);
    }
}

// ---------------------------------------------------------------------------
// KC: cls<25 : Y[b,cls,:] = F25@W1[:128], s25 = F25.Wa + ba
//     cls==25: base[b,:]  = lc@W1[128:] + b1
//     grid(B, 26), block(HID)
// ---------------------------------------------------------------------------
__global__ void kC(const float* __restrict__ Wa,
                   const float* __restrict__ ba,
                   const float* __restrict__ W1,
                   const float* __restrict__ b1) {
    int b = blockIdx.x, cls = blockIdx.y, o = threadIdx.x;
    __shared__ float fs[HID_];
    __shared__ float red[4];

    if (cls == 25) {
        fs[o] = g_lc[b * HID_ + o];
        __syncthreads();
        float acc = b1[o];
        const float* w = W1 + (size_t)HID_ * HID_ + o;
        #pragma unroll 8
        for (int i = 0; i < HID_; i++) acc = fmaf(fs[i], w[i * HID_], acc);
        g_base[b * HID_ + o] = acc;
        return;
    }

    fs[o] = g_F25[(b * 25 + cls) * HID_ + o];
    __syncthreads();

    float a = 0.f;
    #pragma unroll 8
    for (int i = 0; i < HID_; i++) a = fmaf(fs[i], W1[i * HID_ + o], a);
    g_Y[(b * 25 + cls) * HID_ + o] = a;

    float sv = fs[o] * Wa[o];
    for (int off = 16; off >= 1; off >>= 1) sv += __shfl_xor_sync(0xffffffffu, sv, off);
    if ((o & 31) == 0) red[o >> 5] = sv;
    __syncthreads();
    if (o == 0) g_s25[b * 25 + cls] = red[0] + red[1] + red[2] + red[3] + ba[0];
}

// ---------------------------------------------------------------------------
// KD: border-position masked-neighbor attention + MLP -> g_preds
//     grid(NBORD), block(256) : warp w = batch w
// ---------------------------------------------------------------------------
__global__ void kD(const int* __restrict__ mask,
                   const int* __restrict__ nidx,
                   const int* __restrict__ ncnt,
                   const float* __restrict__ W2,
                   const float* __restrict__ b2) {
    int j = blockIdx.x;
    int r, c;
    if (j < 176)      { r = j / 44;            c = j % 44; }
    else if (j < 352) { int j2 = j - 176; r = 89 + j2 / 44; c = j2 % 44; }
    else              { int j3 = j - 352; r = 4 + j3 / 8;
                        int k = j3 % 8; c = (k < 4) ? k : 36 + k; }
    int p = r * W_ + c;

    int warp = threadIdx.x >> 5, lane = threadIdx.x & 31;
    int b = warp;

    __shared__ float wc[8][25];
    if (lane < 25) wc[warp][lane] = 0.f;
    __syncwarp();

    bool has = lane < MAXN_;
    float logit = -3.0e38f;
    int cls = 0;
    if (has) {
        int idx = nidx[p * MAXN_ + lane];
        int rr = idx / W_, c2 = idx % W_;
        int rc = (rr == 0) ? 0 : (rr == 1) ? 1 : (rr == H_ - 2) ? 3 : (rr == H_ - 1) ? 4 : 2;
        int cc = (c2 == 0) ? 0 : (c2 == 1) ? 1 : (c2 == W_ - 2) ? 3 : (c2 == W_ - 1) ? 4 : 2;
        cls = rc * 5 + cc;
        bool valid = (lane < ncnt[p]) && (mask[b * HW_ + idx] == 0);
        logit = valid ? g_s25[b * 25 + cls] : -10000.0f;
    }
    float m = logit;
    for (int off = 16; off >= 1; off >>= 1) m = fmaxf(m, __shfl_xor_sync(0xffffffffu, m, off));
    float e = has ? expf(logit - m) : 0.f;
    float se = e;
    for (int off = 16; off >= 1; off >>= 1) se += __shfl_xor_sync(0xffffffffu, se, off);
    float wgt = e / se;
    if (has && wgt != 0.f) atomicAdd(&wc[warp][cls], wgt);
    __syncwarp();

    float p0 = 0.f, p1 = 0.f;
    for (int k = 0; k < 4; k++) {
        int o = lane + 32 * k;
        float acc = g_base[b * HID_ + o];
        for (int cl = 0; cl < 25; cl++) {
            float wv = wc[warp][cl];
            if (wv != 0.f) acc = fmaf(wv, g_Y[(b * 25 + cl) * HID_ + o], acc);
        }
        float h = gelu_(acc);
        p0 = fmaf(h, W2[o * 2], p0);
        p1 = fmaf(h, W2[o * 2 + 1], p1);
    }
    for (int off = 16; off >= 1; off >>= 1) {
        p0 += __shfl_xor_sync(0xffffffffu, p0, off);
        p1 += __shfl_xor_sync(0xffffffffu, p1, off);
    }
    if (lane == 0) {
        g_preds[(b * HW_ + p) * 2]     = p0 + b2[0];
        g_preds[(b * HW_ + p) * 2 + 1] = p1 + b2[1];
    }
}

// ---------------------------------------------------------------------------
// KE: zero out, compute Pint(b), per-row prefix scan, scatter packed outputs
//     grid(B), block(1024)
// ---------------------------------------------------------------------------
__global__ __launch_bounds__(1024) void kE(const int* __restrict__ mask,
                                           const float* __restrict__ W2,
                                           const float* __restrict__ b2,
                                           float* __restrict__ out) {
    int b = blockIdx.x, t = threadIdx.x;
    int lane = t & 31, warp = t >> 5;
    __shared__ int wsum[32];
    __shared__ float sP[2];

    // --- zero this batch's output slices (float4) ---
    {
        float4 z = make_float4(0.f, 0.f, 0.f, 0.f);
        float4* pr = (float4*)out + (size_t)b * 2046;
        float4* mi = (float4*)(out + OFF1) + (size_t)b * 2046;
        float4* vm = (float4*)(out + OFF2) + (size_t)b * 1023;
        for (int i = t; i < 2046; i += 1024) { pr[i] = z; mi[i] = z; }
        for (int i = t; i < 1023; i += 1024) vm[i] = z;
    }

    // --- interior prediction: Pint = MLP(Y[cls12] + base) (warp 0) ---
    if (t < 32) {
        float p0 = 0.f, p1 = 0.f;
        for (int k = 0; k < 4; k++) {
            int o = t + 32 * k;
            float h = gelu_(g_Y[(b * 25 + 12) * HID_ + o] + g_base[b * HID_ + o]);
            p0 = fmaf(h, W2[o * 2], p0);
            p1 = fmaf(h, W2[o * 2 + 1], p1);
        }
        for (int off = 16; off >= 1; off >>= 1) {
            p0 += __shfl_xor_sync(0xffffffffu, p0, off);
            p1 += __shfl_xor_sync(0xffffffffu, p1, off);
        }
        if (t == 0) { sP[0] = p0 + b2[0]; sP[1] = p1 + b2[1]; }
    }

    // --- per-row scan of mask ---
    int base = t * 4;
    int m[4], loc[4];
    int s = 0;
    for (int j = 0; j < 4; j++) {
        int p = base + j;
        int mm = (p < HW_) ? (mask[b * HW_ + p] > 0) : 0;
        m[j] = mm; loc[j] = s; s += mm;
    }
    int v = s;
    for (int off = 1; off < 32; off <<= 1) {
        int u = __shfl_up_sync(0xffffffffu, v, off);
        if (lane >= off) v += u;
    }
    if (lane == 31) wsum[warp] = v;
    __syncthreads();                       // also orders zeroing + Pint
    if (warp == 0) {
        int wv = wsum[lane];
        for (int off = 1; off < 32; off <<= 1) {
            int u = __shfl_up_sync(0xffffffffu, wv, off);
            if (lane >= off) wv += u;
        }
        wsum[lane] = wv;
    }
    __syncthreads();
    int excl = (v - s) + (warp > 0 ? wsum[warp - 1] : 0);

    float Pi0 = sP[0], Pi1 = sP[1];
    for (int j = 0; j < 4; j++) {
        if (m[j]) {
            int p = base + j;
            int slot = excl + loc[j];
            int r = p / W_, c = p % W_;
            bool interior = (r >= 4 && r <= H_ - 5 && c >= 4 && c <= W_ - 5);
            float v0 = interior ? Pi0 : g_preds[(b * HW_ + p) * 2];
            float v1 = interior ? Pi1 : g_preds[(b * HW_ + p) * 2 + 1];
            out[(b * HW_ + slot) * 2]            = v0;
            out[(b * HW_ + slot) * 2 + 1]        = v1;
            out[OFF1 + (b * HW_ + slot) * 2]     = (float)r;
            out[OFF1 + (b * HW_ + slot) * 2 + 1] = (float)c;
            out[OFF2 + b * HW_ + slot]           = 1.0f;
        }
    }
}

// ---------------------------------------------------------------------------
// kernel_launch
// Inputs: face_tensor, latent_token, mask_2d, nbr_indices, nbr_counts,
//         Wl, bl, Wt, bt, g1, b1g, Wc, bc, Wa, ba, W1, b1, W2, b2
// ---------------------------------------------------------------------------
extern "C" void kernel_launch(void* const* d_in, const int* in_sizes, int n_in,
                              void* d_out, int out_size) {
    const float* latent = (const float*)d_in[1];
    const int*   mask   = (const int*)  d_in[2];
    const int*   nidx   = (const int*)  d_in[3];
    const int*   ncnt   = (const int*)  d_in[4];
    const float* Wl = (const float*)d_in[5];
    const float* bl = (const float*)d_in[6];
    const float* Wt = (const float*)d_in[7];
    const float* bt = (const float*)d_in[8];
    const float* g1 = (const float*)d_in[9];
    const float* b1g= (const float*)d_in[10];
    const float* Wc = (const float*)d_in[11];
    const float* bc = (const float*)d_in[12];
    const float* Wa = (const float*)d_in[13];
    const float* ba = (const float*)d_in[14];
    const float* W1 = (const float*)d_in[15];
    const float* b1 = (const float*)d_in[16];
    const float* W2 = (const float*)d_in[17];
    const float* b2 = (const float*)d_in[18];

    kA<<<B_, 1024>>>(latent, Wl, bl, Wt, bt, g1, b1g);
    { dim3 g(25, 8); kB<<<g, 512>>>(Wc, bc); }
    { dim3 g(B_, 26); kC<<<g, HID_>>>(Wa, ba, W1, b1); }
    kD<<<NBORD, 256>>>(mask, nidx, ncnt, W2, b2);
    kE<<<B_, 1024>>>(mask, W2, b2, (float*)d_out);
}